// round 3
// baseline (speedup 1.0000x reference)
#include <cuda_runtime.h>
#include <math.h>
#include <stdint.h>

// Problem constants
#define NBLK   4
#define DIMC   256
#define DSTATE 16
#define DCONV  4
#define DINC   512          // EXPAND * DIM
#define DTRANK 16
#define BB     16
#define LLEN   512
#define MROWS  (BB * LLEN)  // 8192

// ---------------- scratch (device globals; no allocation allowed) ----------
__device__ float g_h  [(size_t)MROWS * DIMC];       // LN output
__device__ float g_xz [(size_t)MROWS * 2 * DINC];   // in_proj output
__device__ float g_xc [(size_t)MROWS * DINC];       // conv+silu output (u)
__device__ float g_dbc[(size_t)MROWS * 48];         // x_proj output (dt_in|B|C)
__device__ float g_y  [(size_t)MROWS * DINC];       // scan output
__device__ float g_ys [(size_t)MROWS * DINC];       // y * silu(z)

// ---------------- helpers ----------------
__device__ __forceinline__ float silu_f(float v) {
    return __fdividef(v, 1.0f + __expf(-v));
}
__device__ __forceinline__ float softplus_f(float v) {
    return v > 15.0f ? v : log1pf(__expf(v));
}

// ---------------- layernorm ----------------
__global__ void ln_kernel(const float* __restrict__ x,
                          const float* __restrict__ w,
                          const float* __restrict__ b,
                          float* __restrict__ out) {
    int row = blockIdx.x;
    int c   = threadIdx.x;           // 256 threads = DIM
    float v = x[(size_t)row * DIMC + c];
    float s = v, s2 = v * v;
    #pragma unroll
    for (int o = 16; o > 0; o >>= 1) {
        s  += __shfl_xor_sync(0xffffffffu, s,  o);
        s2 += __shfl_xor_sync(0xffffffffu, s2, o);
    }
    __shared__ float sm1[8], sm2[8];
    int wid = c >> 5, lid = c & 31;
    if (lid == 0) { sm1[wid] = s; sm2[wid] = s2; }
    __syncthreads();
    float ts = 0.f, ts2 = 0.f;
    #pragma unroll
    for (int j = 0; j < 8; j++) { ts += sm1[j]; ts2 += sm2[j]; }
    float mu  = ts * (1.0f / DIMC);
    float var = fmaxf(ts2 * (1.0f / DIMC) - mu * mu, 0.0f);
    float inv = rsqrtf(var + 1e-5f);
    out[(size_t)row * DIMC + c] = (v - mu) * inv * w[c] + b[c];
}

// ---------------- generic NT GEMM:  C[M,N] = A[M,K] @ W[N,K]^T (+epilogue) --
// MODE 0: C = acc + bias[col]
// MODE 1: C = acc
// MODE 2: C += acc   (residual accumulate)
template<int MODE>
__global__ __launch_bounds__(256)
void gemm_nt(const float* __restrict__ A, const float* __restrict__ W,
             const float* __restrict__ bias, float* __restrict__ C,
             int Mi, int Ni, int Ki) {
    constexpr int BM = 128, BN = 64, BK = 16;
    __shared__ float As[BK][BM];
    __shared__ float Bs[BK][BN];

    int tid = threadIdx.x;
    int m0 = blockIdx.y * BM;
    int n0 = blockIdx.x * BN;

    int trow = tid >> 4;   // 0..15
    int tcol = tid & 15;   // 0..15

    int ar = tid >> 2;          // 0..63
    int ac = (tid & 3) * 4;     // 0,4,8,12

    float acc[8][4];
    #pragma unroll
    for (int r = 0; r < 8; r++)
        #pragma unroll
        for (int c = 0; c < 4; c++) acc[r][c] = 0.f;

    for (int k0 = 0; k0 < Ki; k0 += BK) {
        // A tile: 128 rows x 16 k
        #pragma unroll
        for (int half = 0; half < 2; half++) {
            int row = ar + half * 64;
            float4 v = *(const float4*)(A + (size_t)(m0 + row) * Ki + k0 + ac);
            As[ac + 0][row] = v.x; As[ac + 1][row] = v.y;
            As[ac + 2][row] = v.z; As[ac + 3][row] = v.w;
        }
        // W tile: 64 cols x 16 k
        {
            int col = ar;
            int cIdx = n0 + col;
            float4 v = make_float4(0.f, 0.f, 0.f, 0.f);
            if (cIdx < Ni) v = *(const float4*)(W + (size_t)cIdx * Ki + k0 + ac);
            Bs[ac + 0][col] = v.x; Bs[ac + 1][col] = v.y;
            Bs[ac + 2][col] = v.z; Bs[ac + 3][col] = v.w;
        }
        __syncthreads();
        #pragma unroll
        for (int kk = 0; kk < BK; kk++) {
            float4 bv = *(const float4*)&Bs[kk][tcol * 4];
            float4 a0 = *(const float4*)&As[kk][trow * 8];
            float4 a1 = *(const float4*)&As[kk][trow * 8 + 4];
            float av[8] = {a0.x, a0.y, a0.z, a0.w, a1.x, a1.y, a1.z, a1.w};
            float bw[4] = {bv.x, bv.y, bv.z, bv.w};
            #pragma unroll
            for (int r = 0; r < 8; r++)
                #pragma unroll
                for (int c = 0; c < 4; c++)
                    acc[r][c] = fmaf(av[r], bw[c], acc[r][c]);
        }
        __syncthreads();
    }

    #pragma unroll
    for (int r = 0; r < 8; r++) {
        int row = m0 + trow * 8 + r;
        #pragma unroll
        for (int c = 0; c < 4; c++) {
            int col = n0 + tcol * 4 + c;
            if (col < Ni) {
                size_t idx = (size_t)row * Ni + col;
                float v = acc[r][c];
                if (MODE == 0) v += bias[col];
                if (MODE == 2) v += C[idx];
                C[idx] = v;
            }
        }
    }
}

// ---------------- depthwise causal conv (k=4) + silu ----------------
__global__ void conv_silu_kernel(const float* __restrict__ xz,
                                 const float* __restrict__ cw,
                                 const float* __restrict__ cb,
                                 float* __restrict__ xc) {
    int idx = blockIdx.x * blockDim.x + threadIdx.x;  // over MROWS*DINC
    int i = idx >> 9;       // row (b*L + t)
    int d = idx & 511;
    int t = i & (LLEN - 1);
    float acc = cb[d];
    #pragma unroll
    for (int k = 0; k < DCONV; k++) {
        int tt = t - 3 + k;
        if (tt >= 0)
            acc = fmaf(xz[(size_t)(i - 3 + k) * (2 * DINC) + d], cw[d * DCONV + k], acc);
    }
    xc[idx] = silu_f(acc);
}

// ---------------- selective scan (dt_proj fused) ----------------
// thread layout: 128 thr/block = 32 d-channels x 4 state-quads; grid (DIN/32, B)
__global__ __launch_bounds__(128)
void scan_kernel(const float* __restrict__ xc, const float* __restrict__ dbc,
                 const float* __restrict__ dtw, const float* __restrict__ dtb,
                 const float* __restrict__ Alog, const float* __restrict__ Dp,
                 float* __restrict__ y) {
    int tid = threadIdx.x;
    int ng = tid & 3;                       // which 4 of the 16 states
    int d  = blockIdx.x * 32 + (tid >> 2);
    int b  = blockIdx.y;

    float4 w4 = *(const float4*)(dtw + d * DTRANK + ng * 4);
    float dtbd = dtb[d];
    float a0 = -expf(Alog[d * DSTATE + ng * 4 + 0]);
    float a1 = -expf(Alog[d * DSTATE + ng * 4 + 1]);
    float a2 = -expf(Alog[d * DSTATE + ng * 4 + 2]);
    float a3 = -expf(Alog[d * DSTATE + ng * 4 + 3]);
    float Dd = Dp[d];

    float h0 = 0.f, h1 = 0.f, h2 = 0.f, h3 = 0.f;
    const float* dbr = dbc + (size_t)b * LLEN * 48;
    const float* ur  = xc  + (size_t)b * LLEN * DINC + d;
    float*       yr  = y   + (size_t)b * LLEN * DINC + d;

    for (int t = 0; t < LLEN; t++) {
        const float* rowp = dbr + t * 48;
        float4 din = *(const float4*)(rowp + ng * 4);
        float part = din.x * w4.x + din.y * w4.y + din.z * w4.z + din.w * w4.w;
        part += __shfl_xor_sync(0xffffffffu, part, 1);
        part += __shfl_xor_sync(0xffffffffu, part, 2);
        float dt = softplus_f(part + dtbd);

        float4 Bv = *(const float4*)(rowp + 16 + ng * 4);
        float4 Cv = *(const float4*)(rowp + 32 + ng * 4);
        float u = ur[(size_t)t * DINC];
        float du = dt * u;

        h0 = fmaf(__expf(dt * a0), h0, du * Bv.x);
        h1 = fmaf(__expf(dt * a1), h1, du * Bv.y);
        h2 = fmaf(__expf(dt * a2), h2, du * Bv.z);
        h3 = fmaf(__expf(dt * a3), h3, du * Bv.w);

        float yp = h0 * Cv.x + h1 * Cv.y + h2 * Cv.z + h3 * Cv.w;
        yp += __shfl_xor_sync(0xffffffffu, yp, 1);
        yp += __shfl_xor_sync(0xffffffffu, yp, 2);
        if (ng == 0) yr[(size_t)t * DINC] = yp + u * Dd;
    }
}

// ---------------- y * silu(z) ----------------
__global__ void ys_kernel(const float* __restrict__ y,
                          const float* __restrict__ xz,
                          float* __restrict__ ys) {
    int idx = blockIdx.x * blockDim.x + threadIdx.x;  // over MROWS*DINC
    int i = idx >> 9;
    int k = idx & 511;
    float z = xz[(size_t)i * (2 * DINC) + DINC + k];
    ys[idx] = y[idx] * silu_f(z);
}

// ---------------- launcher ----------------
extern "C" void kernel_launch(void* const* d_in, const int* in_sizes, int n_in,
                              void* d_out, int out_size) {
    const float* x_in  = (const float*)d_in[0];
    const float* ln_w  = (const float*)d_in[1];
    const float* ln_b  = (const float*)d_in[2];
    const float* in_w  = (const float*)d_in[3];
    const float* in_b  = (const float*)d_in[4];
    const float* cw    = (const float*)d_in[5];
    const float* cb    = (const float*)d_in[6];
    const float* xp_w  = (const float*)d_in[7];
    const float* dtw   = (const float*)d_in[8];
    const float* dtb   = (const float*)d_in[9];
    const float* Alog  = (const float*)d_in[10];
    const float* Dp    = (const float*)d_in[11];
    const float* ow    = (const float*)d_in[12];
    float* xcur = (float*)d_out;

    float *p_h, *p_xz, *p_xc, *p_dbc, *p_y, *p_ys;
    cudaGetSymbolAddress((void**)&p_h,   g_h);
    cudaGetSymbolAddress((void**)&p_xz,  g_xz);
    cudaGetSymbolAddress((void**)&p_xc,  g_xc);
    cudaGetSymbolAddress((void**)&p_dbc, g_dbc);
    cudaGetSymbolAddress((void**)&p_y,   g_y);
    cudaGetSymbolAddress((void**)&p_ys,  g_ys);

    // residual stream lives in d_out
    cudaMemcpyAsync(xcur, x_in, (size_t)MROWS * DIMC * sizeof(float),
                    cudaMemcpyDeviceToDevice);

    const int ELT = MROWS * DINC;           // 4 M elements
    dim3 g1((2 * DINC) / 64, MROWS / 128);  // in_proj: N=1024
    dim3 g2(1,               MROWS / 128);  // x_proj:  N=48
    dim3 g3(DIMC / 64,       MROWS / 128);  // out_proj:N=256

    for (int ib = 0; ib < NBLK; ib++) {
        ln_kernel<<<MROWS, DIMC>>>(xcur, ln_w + ib * DIMC, ln_b + ib * DIMC, p_h);

        gemm_nt<0><<<g1, 256>>>(p_h, in_w + (size_t)ib * 2 * DINC * DIMC,
                                in_b + ib * 2 * DINC, p_xz,
                                MROWS, 2 * DINC, DIMC);

        conv_silu_kernel<<<ELT / 256, 256>>>(p_xz, cw + ib * DINC * DCONV,
                                             cb + ib * DINC, p_xc);

        gemm_nt<1><<<g2, 256>>>(p_xc, xp_w + (size_t)ib * 48 * DINC,
                                nullptr, p_dbc, MROWS, 48, DINC);

        scan_kernel<<<dim3(DINC / 32, BB), 128>>>(
            p_xc, p_dbc, dtw + ib * DINC * DTRANK, dtb + ib * DINC,
            Alog + ib * DINC * DSTATE, Dp + ib * DINC, p_y);

        ys_kernel<<<ELT / 256, 256>>>(p_y, p_xz, p_ys);

        gemm_nt<2><<<g3, 256>>>(p_ys, ow + (size_t)ib * DIMC * DINC,
                                nullptr, xcur, MROWS, DIMC, DINC);
    }
}